// round 14
// baseline (speedup 1.0000x reference)
#include <cuda_runtime.h>
#include <cuda_fp16.h>

#define NN 100000
#define EE 1600000
#define ETOT (EE + NN)
#define GG 64
#define HH 4
#define CC 64
#define NF 32
#define DF 16
#define OO 32
#define HC (HH * CC)
#define SB 512
#define NB ((NN + SB - 1) / SB)   // 196

// k_pre role sizes
#define DPRE_B 16        // GG*CC/256
#define WCONV_B 64       // HC*CC/256
#define WN_B 8           // CC*NF/256
#define ZERO_B 391       // ceil(NN/256)
#define PRE_B (DPRE_B + WCONV_B + WN_B + ZERO_B)

// ---------------- device scratch (static, allocation-free) ----------------
__device__ __align__(16) float  g_h[NN * CC];            // 25.6 MB
__device__ __align__(16) __half g_xh[NN * HC];           // 51.2 MB  [n][h*64+jj]
__device__ __align__(16) __half g_wh[2][HC * CC];
__device__ __align__(16) __half g_wnh[CC * NF];          // node_W fp16
__device__ __align__(16) float  g_as[NN * HH];
__device__ __align__(16) float  g_ad[NN * HH];
__device__ __align__(16) float  g_dpre[GG * CC];
__device__ __align__(16) float  g_vas[2][HH * CC];
__device__ __align__(16) float  g_vad[2][HH * CC];
// CSR
__device__ int g_deg[NN];
__device__ int g_pref[NN];
__device__ int g_bsum[NB];
__device__ int g_boff[NB];
__device__ int g_rowstart[NN];
__device__ int g_cur[NN];
__device__ int g_csrc[ETOT];

// ---------------- helpers ----------------
__device__ __forceinline__ float lrelu(float v) { return v > 0.f ? v : 0.2f * v; }

typedef unsigned long long ull;
__device__ __forceinline__ ull pk2(float lo, float hi) {
    ull r; asm("mov.b64 %0, {%1, %2};" : "=l"(r) : "f"(lo), "f"(hi)); return r;
}
__device__ __forceinline__ ull fma2(ull a, ull b, ull c) {
    ull d; asm("fma.rn.f32x2 %0, %1, %2, %3;" : "=l"(d) : "l"(a), "l"(b), "l"(c)); return d;
}
__device__ __forceinline__ float2 upk2(ull v) {
    float2 f; asm("mov.b64 {%0, %1}, %2;" : "=f"(f.x), "=f"(f.y) : "l"(v)); return f;
}

// ============================================================
// k_pre: dpre | wconv(W0,W1) | wconv(nW) | zerodeg
// ============================================================
__global__ void k_pre(const float* __restrict__ df, const float* __restrict__ dW,
                      const float* __restrict__ db,
                      const float* __restrict__ W0, const float* __restrict__ W1,
                      const float* __restrict__ nW) {
    int bid = blockIdx.x, tid = threadIdx.x;
    if (bid < DPRE_B) {
        int idx = bid * 256 + tid;
        int g = idx / CC, c = idx % CC;
        const float4* a = (const float4*)(df + g * DF);
        const float4* w = (const float4*)(dW + c * DF);
        float acc = db[c];
#pragma unroll
        for (int i = 0; i < DF / 4; i++) {
            float4 av = a[i], wv = w[i];
            acc += av.x * wv.x + av.y * wv.y + av.z * wv.z + av.w * wv.w;
        }
        g_dpre[idx] = acc;
        return;
    }
    bid -= DPRE_B;
    if (bid < WCONV_B) {
        int i = bid * 256 + tid;
        g_wh[0][i] = __float2half(W0[i]);
        g_wh[1][i] = __float2half(W1[i]);
        return;
    }
    bid -= WCONV_B;
    if (bid < WN_B) {
        int i = bid * 256 + tid;
        g_wnh[i] = __float2half(nW[i]);
        return;
    }
    bid -= WN_B;
    int i = bid * 256 + tid;
    if (i < NN) g_deg[i] = 0;
}

// ============================================================
// tensor-core hinit (measured 13us)
// ============================================================
#define HWS 40
__global__ void k_hinit_t(const float* __restrict__ x, const int* __restrict__ batch,
                          const float* __restrict__ nb) {
    __shared__ __half sW[64 * HWS];
    __shared__ __half sX[32 * HWS];
    __shared__ float snb[64];
    int tid = threadIdx.x;
    int base = blockIdx.x * 32;

    {
        int j = tid >> 2, c8 = (tid & 3) * 8;
        *(uint4*)(sW + j * HWS + c8) = *(const uint4*)(g_wnh + j * 32 + c8);
    }
#pragma unroll
    for (int it = 0; it < 4; it++) {
        int idx = it * 256 + tid;
        int n = idx >> 5, c = idx & 31;
        sX[n * HWS + c] = __float2half(x[(size_t)(base + n) * NF + c]);
    }
    if (tid < 64) snb[tid] = nb[tid];
    __syncthreads();

    int warp = tid >> 5, lane = tid & 31;
    int mw = warp & 1;
    int nw = warp >> 1;
    int g = lane >> 2, t = lane & 3;

    float acc[2][4];
#pragma unroll
    for (int b = 0; b < 2; b++)
#pragma unroll
        for (int q = 0; q < 4; q++) acc[b][q] = 0.f;

    const __half* hA0 = sX + (mw * 16 + g) * HWS + t * 2;
    const __half* hA1 = hA0 + 8 * HWS;

#pragma unroll
    for (int k = 0; k < 2; k++) {
        int c0 = k * 16;
        unsigned a0 = *(const unsigned*)(hA0 + c0);
        unsigned a1 = *(const unsigned*)(hA1 + c0);
        unsigned a2 = *(const unsigned*)(hA0 + c0 + 8);
        unsigned a3 = *(const unsigned*)(hA1 + c0 + 8);
#pragma unroll
        for (int b = 0; b < 2; b++) {
            const __half* wB = sW + (nw * 16 + b * 8 + g) * HWS + t * 2;
            unsigned b0 = *(const unsigned*)(wB + c0);
            unsigned b1 = *(const unsigned*)(wB + c0 + 8);
            asm volatile(
                "mma.sync.aligned.m16n8k16.row.col.f32.f16.f16.f32 "
                "{%0,%1,%2,%3}, {%4,%5,%6,%7}, {%8,%9}, {%0,%1,%2,%3};"
                : "+f"(acc[b][0]), "+f"(acc[b][1]), "+f"(acc[b][2]), "+f"(acc[b][3])
                : "r"(a0), "r"(a1), "r"(a2), "r"(a3), "r"(b0), "r"(b1));
        }
    }

    int n0 = base + mw * 16 + g;
    int b0r = batch[n0], b1r = batch[n0 + 8];
#pragma unroll
    for (int b = 0; b < 2; b++) {
        int j = nw * 16 + b * 8 + t * 2;
        float2 d0 = *(const float2*)(g_dpre + (size_t)b0r * 64 + j);
        float2 d1 = *(const float2*)(g_dpre + (size_t)b1r * 64 + j);
        float2 o0, o1;
        o0.x = acc[b][0] + snb[j] + d0.x;
        o0.y = acc[b][1] + snb[j + 1] + d0.y;
        o1.x = acc[b][2] + snb[j] + d1.x;
        o1.y = acc[b][3] + snb[j + 1] + d1.y;
        *(float2*)(g_h + (size_t)n0 * 64 + j) = o0;
        *(float2*)(g_h + (size_t)(n0 + 8) * 64 + j) = o1;
    }
}

// ---------------- CSR build ----------------
__global__ void k_hist(const int* __restrict__ dst) {
    int e = blockIdx.x * blockDim.x + threadIdx.x;
    if (e >= ETOT) return;
    int d = (e < EE) ? dst[e] : e - EE;
    atomicAdd(&g_deg[d], 1);
}

__global__ void k_scan1() {
    __shared__ int wtot[16];
    int tid = threadIdx.x;
    int i = blockIdx.x * SB + tid;
    int v = (i < NN) ? g_deg[i] : 0;
    int lane = tid & 31, w = tid >> 5;
    int s = v;
#pragma unroll
    for (int o = 1; o < 32; o <<= 1) {
        int t = __shfl_up_sync(0xffffffffu, s, o);
        if (lane >= o) s += t;
    }
    if (lane == 31) wtot[w] = s;
    __syncthreads();
    if (w == 0) {
        int tv = (lane < 16) ? wtot[lane] : 0;
#pragma unroll
        for (int o = 1; o < 16; o <<= 1) {
            int t = __shfl_up_sync(0xffffffffu, tv, o);
            if (lane >= o) tv += t;
        }
        if (lane < 16) wtot[lane] = tv;
    }
    __syncthreads();
    int incl = s + ((w == 0) ? 0 : wtot[w - 1]);
    if (i < NN) g_pref[i] = incl;
    if (tid == SB - 1) g_bsum[blockIdx.x] = incl;
}

__global__ void k_scan2() {
    __shared__ int sm[256];
    int t = threadIdx.x;
    sm[t] = (t < NB) ? g_bsum[t] : 0;
    __syncthreads();
    for (int o = 1; o < 256; o <<= 1) {
        int v = (t >= o) ? sm[t - o] : 0;
        __syncthreads();
        sm[t] += v;
        __syncthreads();
    }
    if (t < NB) g_boff[t] = (t == 0) ? 0 : sm[t - 1];
}

__global__ void k_scan3() {
    int i = blockIdx.x * blockDim.x + threadIdx.x;
    if (i >= NN) return;
    int start = g_pref[i] - g_deg[i] + g_boff[i / SB];
    g_rowstart[i] = start;
    g_cur[i] = start;
}

__global__ void k_scat(const int* __restrict__ src, const int* __restrict__ dst) {
    int e = blockIdx.x * blockDim.x + threadIdx.x;
    if (e >= ETOT) return;
    int s, d;
    if (e < EE) { s = src[e]; d = dst[e]; } else { s = e - EE; d = s; }
    int pos = atomicAdd(&g_cur[d], 1);
    g_csrc[pos] = s;
}

// ---------------- va: both layers in one launch ----------------
__global__ void k_va2(const float* __restrict__ W0, const float* __restrict__ as0,
                      const float* __restrict__ ad0,
                      const float* __restrict__ W1, const float* __restrict__ as1,
                      const float* __restrict__ ad1) {
    int t = blockIdx.x * 512 + threadIdx.x;   // [0, 8192)
    int layer = t >> 12;
    int r = t & 4095;
    int j = r >> 3;
    int part = r & 7;
    int which = j >> 8;
    int jj = j & 255;
    int h = jj >> 6, cp = jj & 63;
    const float* W = layer ? W1 : W0;
    const float* a = layer ? (which ? ad1 : as1) : (which ? ad0 : as0);
    float acc = 0.f;
#pragma unroll
    for (int c = part * 8; c < part * 8 + 8; c++)
        acc += a[h * 64 + c] * W[(h * 64 + c) * 64 + cp];
#pragma unroll
    for (int o = 4; o; o >>= 1) acc += __shfl_xor_sync(0xffffffffu, acc, o);
    if (part == 0) (which ? g_vad[layer] : g_vas[layer])[jj] = acc;
}

// ---------------- tensor-core transform + fused alpha epilogue ----------------
#define MT 32
#define WS 72
#define SMEM_MMA ((256 * WS + MT * WS) * 2)    // 41472 bytes
__global__ void k_tmma(int layer) {
    extern __shared__ __half smh[];
    __half* Wsm = smh;                 // [j][c], stride WS
    __half* Hsm = smh + 256 * WS;      // [n][c], stride WS
    int tid = threadIdx.x;
    int base = blockIdx.x * MT;
    const __half* gW = g_wh[layer];

#pragma unroll
    for (int it = 0; it < 8; it++) {
        int idx = it * 256 + tid;
        int j = idx >> 3, c8 = (idx & 7) * 8;
        *(uint4*)(Wsm + j * WS + c8) = *(const uint4*)(gW + j * 64 + c8);
    }
#pragma unroll
    for (int it = 0; it < 4; it++) {
        int idx = it * 256 + tid;
        int n = idx >> 5, c2 = (idx & 31) * 2;
        float2 v = *(const float2*)(g_h + (size_t)(base + n) * 64 + c2);
        *(__half2*)(Hsm + n * WS + c2) = __floats2half2_rn(v.x, v.y);
    }
    __syncthreads();

    int warp = tid >> 5, lane = tid & 31;
    int mw = warp & 1;
    int nw = warp >> 1;
    int g = lane >> 2, t = lane & 3;

    float acc[8][4];
#pragma unroll
    for (int nb = 0; nb < 8; nb++)
#pragma unroll
        for (int q = 0; q < 4; q++) acc[nb][q] = 0.f;

    const __half* hA0 = Hsm + (mw * 16 + g) * WS + t * 2;
    const __half* hA1 = hA0 + 8 * WS;
    const __half* wB = Wsm + (size_t)(nw * 64 + g) * WS + t * 2;

#pragma unroll
    for (int k = 0; k < 4; k++) {
        int c0 = k * 16;
        unsigned a0 = *(const unsigned*)(hA0 + c0);
        unsigned a1 = *(const unsigned*)(hA1 + c0);
        unsigned a2 = *(const unsigned*)(hA0 + c0 + 8);
        unsigned a3 = *(const unsigned*)(hA1 + c0 + 8);
#pragma unroll
        for (int nb = 0; nb < 8; nb++) {
            unsigned b0 = *(const unsigned*)(wB + nb * 8 * WS + c0);
            unsigned b1 = *(const unsigned*)(wB + nb * 8 * WS + c0 + 8);
            asm volatile(
                "mma.sync.aligned.m16n8k16.row.col.f32.f16.f16.f32 "
                "{%0,%1,%2,%3}, {%4,%5,%6,%7}, {%8,%9}, {%0,%1,%2,%3};"
                : "+f"(acc[nb][0]), "+f"(acc[nb][1]), "+f"(acc[nb][2]), "+f"(acc[nb][3])
                : "r"(a0), "r"(a1), "r"(a2), "r"(a3), "r"(b0), "r"(b1));
        }
    }

    int n0 = base + mw * 16 + g;
#pragma unroll
    for (int nb = 0; nb < 8; nb++) {
        int j = nw * 64 + nb * 8 + t * 2;
        *(__half2*)(g_xh + (size_t)n0 * 256 + j) = __floats2half2_rn(acc[nb][0], acc[nb][1]);
        *(__half2*)(g_xh + (size_t)(n0 + 8) * 256 + j) = __floats2half2_rn(acc[nb][2], acc[nb][3]);
    }

    // ---- fused alpha epilogue: as/ad for the 32 nodes from Hsm ----
    // thread -> (node, which, head): n = tid>>3, which = (tid>>2)&1, h = tid&3
    {
        int n = tid >> 3;
        int which = (tid >> 2) & 1;
        int h = tid & 3;
        const float* va = (which ? g_vad[layer] : g_vas[layer]) + h * 64;
        const __half2* hrow = (const __half2*)(Hsm + n * WS);
        float a = 0.f;
#pragma unroll
        for (int i = 0; i < 16; i++) {
            float4 v = __ldg((const float4*)(va + i * 4));
            float2 p0 = __half22float2(hrow[i * 2]);
            float2 p1 = __half22float2(hrow[i * 2 + 1]);
            a += p0.x * v.x + p0.y * v.y + p1.x * v.z + p1.y * v.w;
        }
        (which ? g_ad : g_as)[(size_t)(base + n) * 4 + h] = a;
    }
}

// ---------------- node kernel: f32x2 packed FMA inner loop ----------------
__global__ void __launch_bounds__(256, 6)
k_node(const float* __restrict__ cb, const float* __restrict__ lg,
       const float* __restrict__ lb) {
    __shared__ float se[8][32][4];
    int warp = threadIdx.x >> 5, lane = threadIdx.x & 31;
    int n = blockIdx.x * 8 + warp;
    int row = g_rowstart[n];
    int deg = g_deg[n];
    int my_h = lane >> 3;
    int cbase = (lane & 7) * 8;
    float4 ad4 = *(const float4*)(g_ad + (size_t)n * 4);

    ull a01 = 0ull, a23 = 0ull, a45 = 0ull, a67 = 0ull;
    float4 sum4 = make_float4(0.f, 0.f, 0.f, 0.f);

    for (int base = 0; base < deg; base += 32) {
        int i = base + lane;
        int s_l = 0;
        if (i < deg) {
            s_l = __ldg(g_csrc + row + i);
            float4 a4 = *(const float4*)(g_as + (size_t)s_l * 4);
            float4 e4;
            e4.x = __expf(lrelu(a4.x + ad4.x));
            e4.y = __expf(lrelu(a4.y + ad4.y));
            e4.z = __expf(lrelu(a4.z + ad4.z));
            e4.w = __expf(lrelu(a4.w + ad4.w));
            sum4.x += e4.x; sum4.y += e4.y; sum4.z += e4.z; sum4.w += e4.w;
            *(float4*)&se[warp][lane][0] = e4;
        }
        __syncwarp();
        int cnt = min(32, deg - base);
#pragma unroll 4
        for (int k = 0; k < cnt; k++) {
            int s = __shfl_sync(0xffffffffu, s_l, k);
            float a = se[warp][k][my_h];
            ull aa = pk2(a, a);
            uint4 raw = __ldg((const uint4*)(g_xh + (size_t)s * 256 + lane * 8));
            float2 f0 = __half22float2(*reinterpret_cast<__half2*>(&raw.x));
            float2 f1 = __half22float2(*reinterpret_cast<__half2*>(&raw.y));
            float2 f2 = __half22float2(*reinterpret_cast<__half2*>(&raw.z));
            float2 f3 = __half22float2(*reinterpret_cast<__half2*>(&raw.w));
            a01 = fma2(pk2(f0.x, f0.y), aa, a01);
            a23 = fma2(pk2(f1.x, f1.y), aa, a23);
            a45 = fma2(pk2(f2.x, f2.y), aa, a45);
            a67 = fma2(pk2(f3.x, f3.y), aa, a67);
        }
        __syncwarp();
    }

    float acc[8];
    { float2 r = upk2(a01); acc[0] = r.x; acc[1] = r.y; }
    { float2 r = upk2(a23); acc[2] = r.x; acc[3] = r.y; }
    { float2 r = upk2(a45); acc[4] = r.x; acc[5] = r.y; }
    { float2 r = upk2(a67); acc[6] = r.x; acc[7] = r.y; }

#pragma unroll
    for (int o = 16; o; o >>= 1) {
        sum4.x += __shfl_xor_sync(0xffffffffu, sum4.x, o);
        sum4.y += __shfl_xor_sync(0xffffffffu, sum4.y, o);
        sum4.z += __shfl_xor_sync(0xffffffffu, sum4.z, o);
        sum4.w += __shfl_xor_sync(0xffffffffu, sum4.w, o);
    }
    float sh = (my_h == 0) ? sum4.x : (my_h == 1) ? sum4.y : (my_h == 2) ? sum4.z : sum4.w;
    float rr = 0.25f / (sh + 1e-16f);
#pragma unroll
    for (int k = 0; k < 8; k++) acc[k] *= rr;

#pragma unroll
    for (int k = 0; k < 8; k++) {
        acc[k] += __shfl_xor_sync(0xffffffffu, acc[k], 8);
        acc[k] += __shfl_xor_sync(0xffffffffu, acc[k], 16);
    }

    float v[8], psum = 0.f, psq = 0.f;
#pragma unroll
    for (int k = 0; k < 8; k++) {
        v[k] = acc[k] + cb[cbase + k];
        psum += v[k];
        psq += v[k] * v[k];
    }
#pragma unroll
    for (int o = 4; o; o >>= 1) {
        psum += __shfl_xor_sync(0xffffffffu, psum, o);
        psq  += __shfl_xor_sync(0xffffffffu, psq, o);
    }
    float mu = psum * (1.f / 64.f);
    float var = psq * (1.f / 64.f) - mu * mu;
    float rs = rsqrtf(var + 1e-5f);

    if (lane < 8) {
        float* hp = g_h + (size_t)n * 64 + cbase;
        float4 o0 = *(float4*)hp;
        float4 o1 = *(float4*)(hp + 4);
        float y;
        y = (v[0] - mu) * rs * lg[cbase + 0] + lb[cbase + 0]; o0.x += fmaxf(y, 0.f);
        y = (v[1] - mu) * rs * lg[cbase + 1] + lb[cbase + 1]; o0.y += fmaxf(y, 0.f);
        y = (v[2] - mu) * rs * lg[cbase + 2] + lb[cbase + 2]; o0.z += fmaxf(y, 0.f);
        y = (v[3] - mu) * rs * lg[cbase + 3] + lb[cbase + 3]; o0.w += fmaxf(y, 0.f);
        y = (v[4] - mu) * rs * lg[cbase + 4] + lb[cbase + 4]; o1.x += fmaxf(y, 0.f);
        y = (v[5] - mu) * rs * lg[cbase + 5] + lb[cbase + 5]; o1.y += fmaxf(y, 0.f);
        y = (v[6] - mu) * rs * lg[cbase + 6] + lb[cbase + 6]; o1.z += fmaxf(y, 0.f);
        y = (v[7] - mu) * rs * lg[cbase + 7] + lb[cbase + 7]; o1.w += fmaxf(y, 0.f);
        *(float4*)hp = o0;
        *(float4*)(hp + 4) = o1;
    }
}

// out with smem-staged out_W (conflict-free stride-65 layout).
__global__ void k_out(const float* __restrict__ oW, const float* __restrict__ ob,
                      float* __restrict__ out) {
    __shared__ float sW[32 * 65];
    __shared__ float sob[32];
    for (int i = threadIdx.x; i < 32 * 64; i += 256) {
        int o = i >> 6, k = i & 63;
        sW[o * 65 + k] = oW[i];
    }
    if (threadIdx.x < 32) sob[threadIdx.x] = ob[threadIdx.x];
    __syncthreads();

    int idx = blockIdx.x * 256 + threadIdx.x;   // grid exact NN*OO/256
    int n = idx >> 5, o = idx & 31;
    float acc = sob[o];
    const float4* hr = (const float4*)(g_h + (size_t)n * 64);
    const float* wr = sW + o * 65;
#pragma unroll
    for (int i = 0; i < 16; i++) {
        float4 hv = hr[i];
        acc += hv.x * wr[i * 4] + hv.y * wr[i * 4 + 1]
             + hv.z * wr[i * 4 + 2] + hv.w * wr[i * 4 + 3];
    }
    out[idx] = acc;
}

// ---------------- launch ----------------
extern "C" void kernel_launch(void* const* d_in, const int* in_sizes, int n_in,
                              void* d_out, int out_size) {
    const float* x = (const float*)d_in[0];
    const int* eidx;
    const float* dfeat;
    if (in_sizes[1] == GG * DF) { dfeat = (const float*)d_in[1]; eidx = (const int*)d_in[2]; }
    else                        { eidx = (const int*)d_in[1];    dfeat = (const float*)d_in[2]; }
    const int*   batch = (const int*)d_in[3];
    const float* nW = (const float*)d_in[4];
    const float* nb = (const float*)d_in[5];
    const float* dW = (const float*)d_in[6];
    const float* db = (const float*)d_in[7];
    const float* W0  = (const float*)d_in[8];
    const float* as0 = (const float*)d_in[9];
    const float* ad0 = (const float*)d_in[10];
    const float* cb0 = (const float*)d_in[11];
    const float* lg0 = (const float*)d_in[12];
    const float* lb0 = (const float*)d_in[13];
    const float* W1  = (const float*)d_in[14];
    const float* as1 = (const float*)d_in[15];
    const float* ad1 = (const float*)d_in[16];
    const float* cb1 = (const float*)d_in[17];
    const float* lg1 = (const float*)d_in[18];
    const float* lb1 = (const float*)d_in[19];
    const float* oW = (const float*)d_in[20];
    const float* ob = (const float*)d_in[21];
    const int* srcA = eidx;
    const int* dstA = eidx + EE;

    cudaFuncSetAttribute(k_tmma, cudaFuncAttributeMaxDynamicSharedMemorySize, SMEM_MMA);

    k_pre<<<PRE_B, 256>>>(dfeat, dW, db, W0, W1, nW);                 // 1
    k_hinit_t<<<NN / 32, 256>>>(x, batch, nb);                        // 2
    k_va2<<<16, 512>>>(W0, as0, ad0, W1, as1, ad1);                   // 3
    k_tmma<<<NN / MT, 256, SMEM_MMA>>>(0);                            // 4 <- profiled
    k_hist<<<(ETOT + 255) / 256, 256>>>(dstA);                        // 5
    k_scan1<<<NB, SB>>>();
    k_scan2<<<1, 256>>>();
    k_scan3<<<(NN + 255) / 256, 256>>>();
    k_scat<<<(ETOT + 255) / 256, 256>>>(srcA, dstA);
    k_node<<<NN / 8, 256>>>(cb0, lg0, lb0);

    k_tmma<<<NN / MT, 256, SMEM_MMA>>>(1);
    k_node<<<NN / 8, 256>>>(cb1, lg1, lb1);

    k_out<<<(NN * OO) / 256, 256>>>(oW, ob, (float*)d_out);
}

// round 15
// speedup vs baseline: 1.0756x; 1.0756x over previous
#include <cuda_runtime.h>
#include <cuda_fp16.h>

#define NN 100000
#define EE 1600000
#define ETOT (EE + NN)
#define GG 64
#define HH 4
#define CC 64
#define NF 32
#define DF 16
#define OO 32
#define HC (HH * CC)
#define SB 512
#define NB ((NN + SB - 1) / SB)   // 196

// k_pre role sizes
#define DPRE_B 16        // GG*CC/256
#define WCONV_B 64       // HC*CC/256
#define WN_B 8           // CC*NF/256
#define ZERO_B 391       // ceil(NN/256)
#define PRE_B (DPRE_B + WCONV_B + WN_B + ZERO_B)

// ---------------- device scratch (static, allocation-free) ----------------
__device__ __align__(16) float  g_h[NN * CC];            // 25.6 MB
__device__ __align__(16) __half g_xh[NN * HC];           // 51.2 MB  [n][h*64+jj]
__device__ __align__(16) __half g_wh[2][HC * CC];
__device__ __align__(16) __half g_wnh[CC * NF];          // node_W fp16
__device__ __align__(16) float  g_as[NN * HH];
__device__ __align__(16) float  g_ad[NN * HH];
__device__ __align__(16) float  g_dpre[GG * CC];
__device__ __align__(16) float  g_vas[2][HH * CC];
__device__ __align__(16) float  g_vad[2][HH * CC];
// CSR
__device__ int g_deg[NN];
__device__ int g_pref[NN];
__device__ int g_bsum[NB];
__device__ int g_boff[NB];
__device__ int g_rowstart[NN];
__device__ int g_cur[NN];
__device__ int g_csrc[ETOT];

// ---------------- helpers ----------------
__device__ __forceinline__ float lrelu(float v) { return v > 0.f ? v : 0.2f * v; }

typedef unsigned long long ull;
__device__ __forceinline__ ull pk2(float lo, float hi) {
    ull r; asm("mov.b64 %0, {%1, %2};" : "=l"(r) : "f"(lo), "f"(hi)); return r;
}
__device__ __forceinline__ ull fma2(ull a, ull b, ull c) {
    ull d; asm("fma.rn.f32x2 %0, %1, %2, %3;" : "=l"(d) : "l"(a), "l"(b), "l"(c)); return d;
}
__device__ __forceinline__ float2 upk2(ull v) {
    float2 f; asm("mov.b64 {%0, %1}, %2;" : "=f"(f.x), "=f"(f.y) : "l"(v)); return f;
}

// ============================================================
// k_pre: dpre | wconv(W0,W1) | wconv(nW) | zerodeg
// ============================================================
__global__ void k_pre(const float* __restrict__ df, const float* __restrict__ dW,
                      const float* __restrict__ db,
                      const float* __restrict__ W0, const float* __restrict__ W1,
                      const float* __restrict__ nW) {
    int bid = blockIdx.x, tid = threadIdx.x;
    if (bid < DPRE_B) {
        int idx = bid * 256 + tid;
        int g = idx / CC, c = idx % CC;
        const float4* a = (const float4*)(df + g * DF);
        const float4* w = (const float4*)(dW + c * DF);
        float acc = db[c];
#pragma unroll
        for (int i = 0; i < DF / 4; i++) {
            float4 av = a[i], wv = w[i];
            acc += av.x * wv.x + av.y * wv.y + av.z * wv.z + av.w * wv.w;
        }
        g_dpre[idx] = acc;
        return;
    }
    bid -= DPRE_B;
    if (bid < WCONV_B) {
        int i = bid * 256 + tid;
        g_wh[0][i] = __float2half(W0[i]);
        g_wh[1][i] = __float2half(W1[i]);
        return;
    }
    bid -= WCONV_B;
    if (bid < WN_B) {
        int i = bid * 256 + tid;
        g_wnh[i] = __float2half(nW[i]);
        return;
    }
    bid -= WN_B;
    int i = bid * 256 + tid;
    if (i < NN) g_deg[i] = 0;
}

// ============================================================
// tensor-core hinit (measured 13us)
// ============================================================
#define HWS 40
__global__ void k_hinit_t(const float* __restrict__ x, const int* __restrict__ batch,
                          const float* __restrict__ nb) {
    __shared__ __half sW[64 * HWS];
    __shared__ __half sX[32 * HWS];
    __shared__ float snb[64];
    int tid = threadIdx.x;
    int base = blockIdx.x * 32;

    {
        int j = tid >> 2, c8 = (tid & 3) * 8;
        *(uint4*)(sW + j * HWS + c8) = *(const uint4*)(g_wnh + j * 32 + c8);
    }
#pragma unroll
    for (int it = 0; it < 4; it++) {
        int idx = it * 256 + tid;
        int n = idx >> 5, c = idx & 31;
        sX[n * HWS + c] = __float2half(x[(size_t)(base + n) * NF + c]);
    }
    if (tid < 64) snb[tid] = nb[tid];
    __syncthreads();

    int warp = tid >> 5, lane = tid & 31;
    int mw = warp & 1;
    int nw = warp >> 1;
    int g = lane >> 2, t = lane & 3;

    float acc[2][4];
#pragma unroll
    for (int b = 0; b < 2; b++)
#pragma unroll
        for (int q = 0; q < 4; q++) acc[b][q] = 0.f;

    const __half* hA0 = sX + (mw * 16 + g) * HWS + t * 2;
    const __half* hA1 = hA0 + 8 * HWS;

#pragma unroll
    for (int k = 0; k < 2; k++) {
        int c0 = k * 16;
        unsigned a0 = *(const unsigned*)(hA0 + c0);
        unsigned a1 = *(const unsigned*)(hA1 + c0);
        unsigned a2 = *(const unsigned*)(hA0 + c0 + 8);
        unsigned a3 = *(const unsigned*)(hA1 + c0 + 8);
#pragma unroll
        for (int b = 0; b < 2; b++) {
            const __half* wB = sW + (nw * 16 + b * 8 + g) * HWS + t * 2;
            unsigned b0 = *(const unsigned*)(wB + c0);
            unsigned b1 = *(const unsigned*)(wB + c0 + 8);
            asm volatile(
                "mma.sync.aligned.m16n8k16.row.col.f32.f16.f16.f32 "
                "{%0,%1,%2,%3}, {%4,%5,%6,%7}, {%8,%9}, {%0,%1,%2,%3};"
                : "+f"(acc[b][0]), "+f"(acc[b][1]), "+f"(acc[b][2]), "+f"(acc[b][3])
                : "r"(a0), "r"(a1), "r"(a2), "r"(a3), "r"(b0), "r"(b1));
        }
    }

    int n0 = base + mw * 16 + g;
    int b0r = batch[n0], b1r = batch[n0 + 8];
#pragma unroll
    for (int b = 0; b < 2; b++) {
        int j = nw * 16 + b * 8 + t * 2;
        float2 d0 = *(const float2*)(g_dpre + (size_t)b0r * 64 + j);
        float2 d1 = *(const float2*)(g_dpre + (size_t)b1r * 64 + j);
        float2 o0, o1;
        o0.x = acc[b][0] + snb[j] + d0.x;
        o0.y = acc[b][1] + snb[j + 1] + d0.y;
        o1.x = acc[b][2] + snb[j] + d1.x;
        o1.y = acc[b][3] + snb[j + 1] + d1.y;
        *(float2*)(g_h + (size_t)n0 * 64 + j) = o0;
        *(float2*)(g_h + (size_t)(n0 + 8) * 64 + j) = o1;
    }
}

// ---------------- CSR build ----------------
__global__ void k_hist(const int* __restrict__ dst) {
    int e = blockIdx.x * blockDim.x + threadIdx.x;
    if (e >= ETOT) return;
    int d = (e < EE) ? dst[e] : e - EE;
    atomicAdd(&g_deg[d], 1);
}

__global__ void k_scan1() {
    __shared__ int wtot[16];
    int tid = threadIdx.x;
    int i = blockIdx.x * SB + tid;
    int v = (i < NN) ? g_deg[i] : 0;
    int lane = tid & 31, w = tid >> 5;
    int s = v;
#pragma unroll
    for (int o = 1; o < 32; o <<= 1) {
        int t = __shfl_up_sync(0xffffffffu, s, o);
        if (lane >= o) s += t;
    }
    if (lane == 31) wtot[w] = s;
    __syncthreads();
    if (w == 0) {
        int tv = (lane < 16) ? wtot[lane] : 0;
#pragma unroll
        for (int o = 1; o < 16; o <<= 1) {
            int t = __shfl_up_sync(0xffffffffu, tv, o);
            if (lane >= o) tv += t;
        }
        if (lane < 16) wtot[lane] = tv;
    }
    __syncthreads();
    int incl = s + ((w == 0) ? 0 : wtot[w - 1]);
    if (i < NN) g_pref[i] = incl;
    if (tid == SB - 1) g_bsum[blockIdx.x] = incl;
}

__global__ void k_scan2() {
    __shared__ int sm[256];
    int t = threadIdx.x;
    sm[t] = (t < NB) ? g_bsum[t] : 0;
    __syncthreads();
    for (int o = 1; o < 256; o <<= 1) {
        int v = (t >= o) ? sm[t - o] : 0;
        __syncthreads();
        sm[t] += v;
        __syncthreads();
    }
    if (t < NB) g_boff[t] = (t == 0) ? 0 : sm[t - 1];
}

__global__ void k_scan3() {
    int i = blockIdx.x * blockDim.x + threadIdx.x;
    if (i >= NN) return;
    int start = g_pref[i] - g_deg[i] + g_boff[i / SB];
    g_rowstart[i] = start;
    g_cur[i] = start;
}

__global__ void k_scat(const int* __restrict__ src, const int* __restrict__ dst) {
    int e = blockIdx.x * blockDim.x + threadIdx.x;
    if (e >= ETOT) return;
    int s, d;
    if (e < EE) { s = src[e]; d = dst[e]; } else { s = e - EE; d = s; }
    int pos = atomicAdd(&g_cur[d], 1);
    g_csrc[pos] = s;
}

// ---------------- va: both layers in one launch ----------------
__global__ void k_va2(const float* __restrict__ W0, const float* __restrict__ as0,
                      const float* __restrict__ ad0,
                      const float* __restrict__ W1, const float* __restrict__ as1,
                      const float* __restrict__ ad1) {
    int t = blockIdx.x * 512 + threadIdx.x;   // [0, 8192)
    int layer = t >> 12;
    int r = t & 4095;
    int j = r >> 3;
    int part = r & 7;
    int which = j >> 8;
    int jj = j & 255;
    int h = jj >> 6, cp = jj & 63;
    const float* W = layer ? W1 : W0;
    const float* a = layer ? (which ? ad1 : as1) : (which ? ad0 : as0);
    float acc = 0.f;
#pragma unroll
    for (int c = part * 8; c < part * 8 + 8; c++)
        acc += a[h * 64 + c] * W[(h * 64 + c) * 64 + cp];
#pragma unroll
    for (int o = 4; o; o >>= 1) acc += __shfl_xor_sync(0xffffffffu, acc, o);
    if (part == 0) (which ? g_vad[layer] : g_vas[layer])[jj] = acc;
}

// ---------------- alpha (standalone, layer-indexed) ----------------
__global__ void k_alpha(int layer) {
    int idx = blockIdx.x * blockDim.x + threadIdx.x;
    if (idx >= NN * HH) return;
    int n = idx >> 2, h = idx & 3;
    const float4* hr = (const float4*)(g_h + (size_t)n * CC);
    const float4* vs = (const float4*)(g_vas[layer] + h * CC);
    const float4* vd = (const float4*)(g_vad[layer] + h * CC);
    float s = 0.f, d = 0.f;
#pragma unroll
    for (int i = 0; i < CC / 4; i++) {
        float4 hv = hr[i], sv = vs[i], dv = vd[i];
        s += hv.x * sv.x + hv.y * sv.y + hv.z * sv.z + hv.w * sv.w;
        d += hv.x * dv.x + hv.y * dv.y + hv.z * dv.z + hv.w * dv.w;
    }
    g_as[idx] = s;
    g_ad[idx] = d;
}

// ---------------- tensor-core transform (R13 version, measured 35us) ----------------
#define MT 32
#define WS 72
#define SMEM_MMA ((256 * WS + MT * WS) * 2)    // 41472 bytes
__global__ void k_tmma(int layer) {
    extern __shared__ __half smh[];
    __half* Wsm = smh;                 // [j][c], stride WS
    __half* Hsm = smh + 256 * WS;      // [n][c], stride WS
    int tid = threadIdx.x;
    int base = blockIdx.x * MT;
    const __half* gW = g_wh[layer];

#pragma unroll
    for (int it = 0; it < 8; it++) {
        int idx = it * 256 + tid;
        int j = idx >> 3, c8 = (idx & 7) * 8;
        *(uint4*)(Wsm + j * WS + c8) = *(const uint4*)(gW + j * 64 + c8);
    }
#pragma unroll
    for (int it = 0; it < 4; it++) {
        int idx = it * 256 + tid;
        int n = idx >> 5, c2 = (idx & 31) * 2;
        float2 v = *(const float2*)(g_h + (size_t)(base + n) * 64 + c2);
        *(__half2*)(Hsm + n * WS + c2) = __floats2half2_rn(v.x, v.y);
    }
    __syncthreads();

    int warp = tid >> 5, lane = tid & 31;
    int mw = warp & 1;
    int nw = warp >> 1;
    int g = lane >> 2, t = lane & 3;

    float acc[8][4];
#pragma unroll
    for (int nb = 0; nb < 8; nb++)
#pragma unroll
        for (int q = 0; q < 4; q++) acc[nb][q] = 0.f;

    const __half* hA0 = Hsm + (mw * 16 + g) * WS + t * 2;
    const __half* hA1 = hA0 + 8 * WS;
    const __half* wB = Wsm + (size_t)(nw * 64 + g) * WS + t * 2;

#pragma unroll
    for (int k = 0; k < 4; k++) {
        int c0 = k * 16;
        unsigned a0 = *(const unsigned*)(hA0 + c0);
        unsigned a1 = *(const unsigned*)(hA1 + c0);
        unsigned a2 = *(const unsigned*)(hA0 + c0 + 8);
        unsigned a3 = *(const unsigned*)(hA1 + c0 + 8);
#pragma unroll
        for (int nb = 0; nb < 8; nb++) {
            unsigned b0 = *(const unsigned*)(wB + nb * 8 * WS + c0);
            unsigned b1 = *(const unsigned*)(wB + nb * 8 * WS + c0 + 8);
            asm volatile(
                "mma.sync.aligned.m16n8k16.row.col.f32.f16.f16.f32 "
                "{%0,%1,%2,%3}, {%4,%5,%6,%7}, {%8,%9}, {%0,%1,%2,%3};"
                : "+f"(acc[nb][0]), "+f"(acc[nb][1]), "+f"(acc[nb][2]), "+f"(acc[nb][3])
                : "r"(a0), "r"(a1), "r"(a2), "r"(a3), "r"(b0), "r"(b1));
        }
    }

    int n0 = base + mw * 16 + g;
#pragma unroll
    for (int nb = 0; nb < 8; nb++) {
        int j = nw * 64 + nb * 8 + t * 2;
        *(__half2*)(g_xh + (size_t)n0 * 256 + j) = __floats2half2_rn(acc[nb][0], acc[nb][1]);
        *(__half2*)(g_xh + (size_t)(n0 + 8) * 256 + j) = __floats2half2_rn(acc[nb][2], acc[nb][3]);
    }
}

// ---------------- node kernel: f32x2 packed FMA (R14, measured ~99us) ----------------
__global__ void __launch_bounds__(256, 6)
k_node(const float* __restrict__ cb, const float* __restrict__ lg,
       const float* __restrict__ lb) {
    __shared__ float se[8][32][4];
    int warp = threadIdx.x >> 5, lane = threadIdx.x & 31;
    int n = blockIdx.x * 8 + warp;
    int row = g_rowstart[n];
    int deg = g_deg[n];
    int my_h = lane >> 3;
    int cbase = (lane & 7) * 8;
    float4 ad4 = *(const float4*)(g_ad + (size_t)n * 4);

    ull a01 = 0ull, a23 = 0ull, a45 = 0ull, a67 = 0ull;
    float4 sum4 = make_float4(0.f, 0.f, 0.f, 0.f);

    for (int base = 0; base < deg; base += 32) {
        int i = base + lane;
        int s_l = 0;
        if (i < deg) {
            s_l = __ldg(g_csrc + row + i);
            float4 a4 = *(const float4*)(g_as + (size_t)s_l * 4);
            float4 e4;
            e4.x = __expf(lrelu(a4.x + ad4.x));
            e4.y = __expf(lrelu(a4.y + ad4.y));
            e4.z = __expf(lrelu(a4.z + ad4.z));
            e4.w = __expf(lrelu(a4.w + ad4.w));
            sum4.x += e4.x; sum4.y += e4.y; sum4.z += e4.z; sum4.w += e4.w;
            *(float4*)&se[warp][lane][0] = e4;
        }
        __syncwarp();
        int cnt = min(32, deg - base);
#pragma unroll 4
        for (int k = 0; k < cnt; k++) {
            int s = __shfl_sync(0xffffffffu, s_l, k);
            float a = se[warp][k][my_h];
            ull aa = pk2(a, a);
            uint4 raw = __ldg((const uint4*)(g_xh + (size_t)s * 256 + lane * 8));
            float2 f0 = __half22float2(*reinterpret_cast<__half2*>(&raw.x));
            float2 f1 = __half22float2(*reinterpret_cast<__half2*>(&raw.y));
            float2 f2 = __half22float2(*reinterpret_cast<__half2*>(&raw.z));
            float2 f3 = __half22float2(*reinterpret_cast<__half2*>(&raw.w));
            a01 = fma2(pk2(f0.x, f0.y), aa, a01);
            a23 = fma2(pk2(f1.x, f1.y), aa, a23);
            a45 = fma2(pk2(f2.x, f2.y), aa, a45);
            a67 = fma2(pk2(f3.x, f3.y), aa, a67);
        }
        __syncwarp();
    }

    float acc[8];
    { float2 r = upk2(a01); acc[0] = r.x; acc[1] = r.y; }
    { float2 r = upk2(a23); acc[2] = r.x; acc[3] = r.y; }
    { float2 r = upk2(a45); acc[4] = r.x; acc[5] = r.y; }
    { float2 r = upk2(a67); acc[6] = r.x; acc[7] = r.y; }

#pragma unroll
    for (int o = 16; o; o >>= 1) {
        sum4.x += __shfl_xor_sync(0xffffffffu, sum4.x, o);
        sum4.y += __shfl_xor_sync(0xffffffffu, sum4.y, o);
        sum4.z += __shfl_xor_sync(0xffffffffu, sum4.z, o);
        sum4.w += __shfl_xor_sync(0xffffffffu, sum4.w, o);
    }
    float sh = (my_h == 0) ? sum4.x : (my_h == 1) ? sum4.y : (my_h == 2) ? sum4.z : sum4.w;
    float rr = 0.25f / (sh + 1e-16f);
#pragma unroll
    for (int k = 0; k < 8; k++) acc[k] *= rr;

#pragma unroll
    for (int k = 0; k < 8; k++) {
        acc[k] += __shfl_xor_sync(0xffffffffu, acc[k], 8);
        acc[k] += __shfl_xor_sync(0xffffffffu, acc[k], 16);
    }

    float v[8], psum = 0.f, psq = 0.f;
#pragma unroll
    for (int k = 0; k < 8; k++) {
        v[k] = acc[k] + cb[cbase + k];
        psum += v[k];
        psq += v[k] * v[k];
    }
#pragma unroll
    for (int o = 4; o; o >>= 1) {
        psum += __shfl_xor_sync(0xffffffffu, psum, o);
        psq  += __shfl_xor_sync(0xffffffffu, psq, o);
    }
    float mu = psum * (1.f / 64.f);
    float var = psq * (1.f / 64.f) - mu * mu;
    float rs = rsqrtf(var + 1e-5f);

    if (lane < 8) {
        float* hp = g_h + (size_t)n * 64 + cbase;
        float4 o0 = *(float4*)hp;
        float4 o1 = *(float4*)(hp + 4);
        float y;
        y = (v[0] - mu) * rs * lg[cbase + 0] + lb[cbase + 0]; o0.x += fmaxf(y, 0.f);
        y = (v[1] - mu) * rs * lg[cbase + 1] + lb[cbase + 1]; o0.y += fmaxf(y, 0.f);
        y = (v[2] - mu) * rs * lg[cbase + 2] + lb[cbase + 2]; o0.z += fmaxf(y, 0.f);
        y = (v[3] - mu) * rs * lg[cbase + 3] + lb[cbase + 3]; o0.w += fmaxf(y, 0.f);
        y = (v[4] - mu) * rs * lg[cbase + 4] + lb[cbase + 4]; o1.x += fmaxf(y, 0.f);
        y = (v[5] - mu) * rs * lg[cbase + 5] + lb[cbase + 5]; o1.y += fmaxf(y, 0.f);
        y = (v[6] - mu) * rs * lg[cbase + 6] + lb[cbase + 6]; o1.z += fmaxf(y, 0.f);
        y = (v[7] - mu) * rs * lg[cbase + 7] + lb[cbase + 7]; o1.w += fmaxf(y, 0.f);
        *(float4*)hp = o0;
        *(float4*)(hp + 4) = o1;
    }
}

// out with smem-staged out_W (conflict-free stride-65 layout).
__global__ void k_out(const float* __restrict__ oW, const float* __restrict__ ob,
                      float* __restrict__ out) {
    __shared__ float sW[32 * 65];
    __shared__ float sob[32];
    for (int i = threadIdx.x; i < 32 * 64; i += 256) {
        int o = i >> 6, k = i & 63;
        sW[o * 65 + k] = oW[i];
    }
    if (threadIdx.x < 32) sob[threadIdx.x] = ob[threadIdx.x];
    __syncthreads();

    int idx = blockIdx.x * 256 + threadIdx.x;   // grid exact NN*OO/256
    int n = idx >> 5, o = idx & 31;
    float acc = sob[o];
    const float4* hr = (const float4*)(g_h + (size_t)n * 64);
    const float* wr = sW + o * 65;
#pragma unroll
    for (int i = 0; i < 16; i++) {
        float4 hv = hr[i];
        acc += hv.x * wr[i * 4] + hv.y * wr[i * 4 + 1]
             + hv.z * wr[i * 4 + 2] + hv.w * wr[i * 4 + 3];
    }
    out[idx] = acc;
}

// ---------------- launch ----------------
extern "C" void kernel_launch(void* const* d_in, const int* in_sizes, int n_in,
                              void* d_out, int out_size) {
    const float* x = (const float*)d_in[0];
    const int* eidx;
    const float* dfeat;
    if (in_sizes[1] == GG * DF) { dfeat = (const float*)d_in[1]; eidx = (const int*)d_in[2]; }
    else                        { eidx = (const int*)d_in[1];    dfeat = (const float*)d_in[2]; }
    const int*   batch = (const int*)d_in[3];
    const float* nW = (const float*)d_in[4];
    const float* nb = (const float*)d_in[5];
    const float* dW = (const float*)d_in[6];
    const float* db = (const float*)d_in[7];
    const float* W0  = (const float*)d_in[8];
    const float* as0 = (const float*)d_in[9];
    const float* ad0 = (const float*)d_in[10];
    const float* cb0 = (const float*)d_in[11];
    const float* lg0 = (const float*)d_in[12];
    const float* lb0 = (const float*)d_in[13];
    const float* W1  = (const float*)d_in[14];
    const float* as1 = (const float*)d_in[15];
    const float* ad1 = (const float*)d_in[16];
    const float* cb1 = (const float*)d_in[17];
    const float* lg1 = (const float*)d_in[18];
    const float* lb1 = (const float*)d_in[19];
    const float* oW = (const float*)d_in[20];
    const float* ob = (const float*)d_in[21];
    const int* srcA = eidx;
    const int* dstA = eidx + EE;

    cudaFuncSetAttribute(k_tmma, cudaFuncAttributeMaxDynamicSharedMemorySize, SMEM_MMA);

    k_pre<<<PRE_B, 256>>>(dfeat, dW, db, W0, W1, nW);                 // 1
    k_hinit_t<<<NN / 32, 256>>>(x, batch, nb);                        // 2
    k_va2<<<16, 512>>>(W0, as0, ad0, W1, as1, ad1);                   // 3
    k_tmma<<<NN / MT, 256, SMEM_MMA>>>(0);                            // 4 <- profiled
    k_alpha<<<(NN * HH + 255) / 256, 256>>>(0);                       // 5
    k_hist<<<(ETOT + 255) / 256, 256>>>(dstA);
    k_scan1<<<NB, SB>>>();
    k_scan2<<<1, 256>>>();
    k_scan3<<<(NN + 255) / 256, 256>>>();
    k_scat<<<(ETOT + 255) / 256, 256>>>(srcA, dstA);
    k_node<<<NN / 8, 256>>>(cb0, lg0, lb0);

    k_alpha<<<(NN * HH + 255) / 256, 256>>>(1);
    k_tmma<<<NN / MT, 256, SMEM_MMA>>>(1);
    k_node<<<NN / 8, 256>>>(cb1, lg1, lb1);

    k_out<<<(NN * OO) / 256, 256>>>(oW, ob, (float*)d_out);
}

// round 16
// speedup vs baseline: 1.1705x; 1.0881x over previous
#include <cuda_runtime.h>
#include <cuda_fp16.h>

#define NN 100000
#define EE 1600000
#define ETOT (EE + NN)
#define GG 64
#define HH 4
#define CC 64
#define NF 32
#define DF 16
#define OO 32
#define HC (HH * CC)
#define SB 512
#define NB ((NN + SB - 1) / SB)   // 196

// k_pre role sizes
#define DPRE_B 16        // GG*CC/256
#define WCONV_B 64       // HC*CC/256
#define WN_B 8           // CC*NF/256
#define ZERO_B 391       // ceil(NN/256)
#define PRE_B (DPRE_B + WCONV_B + WN_B + ZERO_B)

// ---------------- device scratch (static, allocation-free) ----------------
__device__ __align__(16) float  g_h[NN * CC];            // 25.6 MB
__device__ __align__(16) __half g_xh[NN * HC];           // 51.2 MB  [n][h*64+jj]
__device__ __align__(16) __half g_wh[2][HC * CC];
__device__ __align__(16) __half g_wnh[CC * NF];          // node_W fp16
__device__ __align__(16) float  g_as[NN * HH];
__device__ __align__(16) float  g_ad[NN * HH];
__device__ __align__(16) float  g_dpre[GG * CC];
__device__ __align__(16) float  g_vas[2][HH * CC];
__device__ __align__(16) float  g_vad[2][HH * CC];
// CSR
__device__ int g_deg[NN];
__device__ int g_pref[NN];
__device__ int g_bsum[NB];
__device__ int g_boff[NB];
__device__ int g_rowstart[NN];
__device__ int g_cur[NN];
__device__ int g_csrc[ETOT];

// ---------------- helpers ----------------
__device__ __forceinline__ float lrelu(float v) { return v > 0.f ? v : 0.2f * v; }

typedef unsigned long long ull;
__device__ __forceinline__ ull pk2(float lo, float hi) {
    ull r; asm("mov.b64 %0, {%1, %2};" : "=l"(r) : "f"(lo), "f"(hi)); return r;
}
__device__ __forceinline__ ull fma2(ull a, ull b, ull c) {
    ull d; asm("fma.rn.f32x2 %0, %1, %2, %3;" : "=l"(d) : "l"(a), "l"(b), "l"(c)); return d;
}
__device__ __forceinline__ float2 upk2(ull v) {
    float2 f; asm("mov.b64 {%0, %1}, %2;" : "=f"(f.x), "=f"(f.y) : "l"(v)); return f;
}

// ============================================================
// k_pre: dpre | wconv(W0,W1) | wconv(nW) | zerodeg
// ============================================================
__global__ void k_pre(const float* __restrict__ df, const float* __restrict__ dW,
                      const float* __restrict__ db,
                      const float* __restrict__ W0, const float* __restrict__ W1,
                      const float* __restrict__ nW) {
    int bid = blockIdx.x, tid = threadIdx.x;
    if (bid < DPRE_B) {
        int idx = bid * 256 + tid;
        int g = idx / CC, c = idx % CC;
        const float4* a = (const float4*)(df + g * DF);
        const float4* w = (const float4*)(dW + c * DF);
        float acc = db[c];
#pragma unroll
        for (int i = 0; i < DF / 4; i++) {
            float4 av = a[i], wv = w[i];
            acc += av.x * wv.x + av.y * wv.y + av.z * wv.z + av.w * wv.w;
        }
        g_dpre[idx] = acc;
        return;
    }
    bid -= DPRE_B;
    if (bid < WCONV_B) {
        int i = bid * 256 + tid;
        g_wh[0][i] = __float2half(W0[i]);
        g_wh[1][i] = __float2half(W1[i]);
        return;
    }
    bid -= WCONV_B;
    if (bid < WN_B) {
        int i = bid * 256 + tid;
        g_wnh[i] = __float2half(nW[i]);
        return;
    }
    bid -= WN_B;
    int i = bid * 256 + tid;
    if (i < NN) g_deg[i] = 0;
}

// ============================================================
// tensor-core hinit (measured 13us)
// ============================================================
#define HWS 40
__global__ void k_hinit_t(const float* __restrict__ x, const int* __restrict__ batch,
                          const float* __restrict__ nb) {
    __shared__ __half sW[64 * HWS];
    __shared__ __half sX[32 * HWS];
    __shared__ float snb[64];
    int tid = threadIdx.x;
    int base = blockIdx.x * 32;

    {
        int j = tid >> 2, c8 = (tid & 3) * 8;
        *(uint4*)(sW + j * HWS + c8) = *(const uint4*)(g_wnh + j * 32 + c8);
    }
#pragma unroll
    for (int it = 0; it < 4; it++) {
        int idx = it * 256 + tid;
        int n = idx >> 5, c = idx & 31;
        sX[n * HWS + c] = __float2half(x[(size_t)(base + n) * NF + c]);
    }
    if (tid < 64) snb[tid] = nb[tid];
    __syncthreads();

    int warp = tid >> 5, lane = tid & 31;
    int mw = warp & 1;
    int nw = warp >> 1;
    int g = lane >> 2, t = lane & 3;

    float acc[2][4];
#pragma unroll
    for (int b = 0; b < 2; b++)
#pragma unroll
        for (int q = 0; q < 4; q++) acc[b][q] = 0.f;

    const __half* hA0 = sX + (mw * 16 + g) * HWS + t * 2;
    const __half* hA1 = hA0 + 8 * HWS;

#pragma unroll
    for (int k = 0; k < 2; k++) {
        int c0 = k * 16;
        unsigned a0 = *(const unsigned*)(hA0 + c0);
        unsigned a1 = *(const unsigned*)(hA1 + c0);
        unsigned a2 = *(const unsigned*)(hA0 + c0 + 8);
        unsigned a3 = *(const unsigned*)(hA1 + c0 + 8);
#pragma unroll
        for (int b = 0; b < 2; b++) {
            const __half* wB = sW + (nw * 16 + b * 8 + g) * HWS + t * 2;
            unsigned b0 = *(const unsigned*)(wB + c0);
            unsigned b1 = *(const unsigned*)(wB + c0 + 8);
            asm volatile(
                "mma.sync.aligned.m16n8k16.row.col.f32.f16.f16.f32 "
                "{%0,%1,%2,%3}, {%4,%5,%6,%7}, {%8,%9}, {%0,%1,%2,%3};"
                : "+f"(acc[b][0]), "+f"(acc[b][1]), "+f"(acc[b][2]), "+f"(acc[b][3])
                : "r"(a0), "r"(a1), "r"(a2), "r"(a3), "r"(b0), "r"(b1));
        }
    }

    int n0 = base + mw * 16 + g;
    int b0r = batch[n0], b1r = batch[n0 + 8];
#pragma unroll
    for (int b = 0; b < 2; b++) {
        int j = nw * 16 + b * 8 + t * 2;
        float2 d0 = *(const float2*)(g_dpre + (size_t)b0r * 64 + j);
        float2 d1 = *(const float2*)(g_dpre + (size_t)b1r * 64 + j);
        float2 o0, o1;
        o0.x = acc[b][0] + snb[j] + d0.x;
        o0.y = acc[b][1] + snb[j + 1] + d0.y;
        o1.x = acc[b][2] + snb[j] + d1.x;
        o1.y = acc[b][3] + snb[j + 1] + d1.y;
        *(float2*)(g_h + (size_t)n0 * 64 + j) = o0;
        *(float2*)(g_h + (size_t)(n0 + 8) * 64 + j) = o1;
    }
}

// ---------------- CSR build ----------------
__global__ void k_hist(const int* __restrict__ dst) {
    int e = blockIdx.x * blockDim.x + threadIdx.x;
    if (e >= ETOT) return;
    int d = (e < EE) ? dst[e] : e - EE;
    atomicAdd(&g_deg[d], 1);
}

__global__ void k_scan1() {
    __shared__ int wtot[16];
    int tid = threadIdx.x;
    int i = blockIdx.x * SB + tid;
    int v = (i < NN) ? g_deg[i] : 0;
    int lane = tid & 31, w = tid >> 5;
    int s = v;
#pragma unroll
    for (int o = 1; o < 32; o <<= 1) {
        int t = __shfl_up_sync(0xffffffffu, s, o);
        if (lane >= o) s += t;
    }
    if (lane == 31) wtot[w] = s;
    __syncthreads();
    if (w == 0) {
        int tv = (lane < 16) ? wtot[lane] : 0;
#pragma unroll
        for (int o = 1; o < 16; o <<= 1) {
            int t = __shfl_up_sync(0xffffffffu, tv, o);
            if (lane >= o) tv += t;
        }
        if (lane < 16) wtot[lane] = tv;
    }
    __syncthreads();
    int incl = s + ((w == 0) ? 0 : wtot[w - 1]);
    if (i < NN) g_pref[i] = incl;
    if (tid == SB - 1) g_bsum[blockIdx.x] = incl;
}

__global__ void k_scan2() {
    __shared__ int sm[256];
    int t = threadIdx.x;
    sm[t] = (t < NB) ? g_bsum[t] : 0;
    __syncthreads();
    for (int o = 1; o < 256; o <<= 1) {
        int v = (t >= o) ? sm[t - o] : 0;
        __syncthreads();
        sm[t] += v;
        __syncthreads();
    }
    if (t < NB) g_boff[t] = (t == 0) ? 0 : sm[t - 1];
}

__global__ void k_scan3() {
    int i = blockIdx.x * blockDim.x + threadIdx.x;
    if (i >= NN) return;
    int start = g_pref[i] - g_deg[i] + g_boff[i / SB];
    g_rowstart[i] = start;
    g_cur[i] = start;
}

__global__ void k_scat(const int* __restrict__ src, const int* __restrict__ dst) {
    int e = blockIdx.x * blockDim.x + threadIdx.x;
    if (e >= ETOT) return;
    int s, d;
    if (e < EE) { s = src[e]; d = dst[e]; } else { s = e - EE; d = s; }
    int pos = atomicAdd(&g_cur[d], 1);
    g_csrc[pos] = s;
}

// ---------------- va: both layers in one launch ----------------
__global__ void k_va2(const float* __restrict__ W0, const float* __restrict__ as0,
                      const float* __restrict__ ad0,
                      const float* __restrict__ W1, const float* __restrict__ as1,
                      const float* __restrict__ ad1) {
    int t = blockIdx.x * 512 + threadIdx.x;   // [0, 8192)
    int layer = t >> 12;
    int r = t & 4095;
    int j = r >> 3;
    int part = r & 7;
    int which = j >> 8;
    int jj = j & 255;
    int h = jj >> 6, cp = jj & 63;
    const float* W = layer ? W1 : W0;
    const float* a = layer ? (which ? ad1 : as1) : (which ? ad0 : as0);
    float acc = 0.f;
#pragma unroll
    for (int c = part * 8; c < part * 8 + 8; c++)
        acc += a[h * 64 + c] * W[(h * 64 + c) * 64 + cp];
#pragma unroll
    for (int o = 4; o; o >>= 1) acc += __shfl_xor_sync(0xffffffffu, acc, o);
    if (part == 0) (which ? g_vad[layer] : g_vas[layer])[jj] = acc;
}

// ---------------- alpha: one warp per node, h read once ----------------
__global__ void k_alpha(int layer) {
    int w = (blockIdx.x * 256 + threadIdx.x) >> 5;   // node id
    int lane = threadIdx.x & 31;
    if (w >= NN) return;
    int c = lane * 2;
    float2 hv = *(const float2*)(g_h + (size_t)w * 64 + c);
    const float* vsb = g_vas[layer];
    const float* vdb = g_vad[layer];
    float r[8];
#pragma unroll
    for (int h = 0; h < 4; h++) {
        float2 vs = *(const float2*)(vsb + h * 64 + c);
        float2 vd = *(const float2*)(vdb + h * 64 + c);
        r[h]     = hv.x * vs.x + hv.y * vs.y;
        r[4 + h] = hv.x * vd.x + hv.y * vd.y;
    }
#pragma unroll
    for (int o = 16; o; o >>= 1)
#pragma unroll
        for (int k = 0; k < 8; k++)
            r[k] += __shfl_xor_sync(0xffffffffu, r[k], o);
    if (lane < 4)      g_as[(size_t)w * 4 + lane] = r[lane];
    else if (lane < 8) g_ad[(size_t)w * 4 + lane - 4] = r[lane];
}

// ---------------- tensor-core transform (R13 version, measured 35us) ----------------
#define MT 32
#define WS 72
#define SMEM_MMA ((256 * WS + MT * WS) * 2)    // 41472 bytes
__global__ void k_tmma(int layer) {
    extern __shared__ __half smh[];
    __half* Wsm = smh;                 // [j][c], stride WS
    __half* Hsm = smh + 256 * WS;      // [n][c], stride WS
    int tid = threadIdx.x;
    int base = blockIdx.x * MT;
    const __half* gW = g_wh[layer];

#pragma unroll
    for (int it = 0; it < 8; it++) {
        int idx = it * 256 + tid;
        int j = idx >> 3, c8 = (idx & 7) * 8;
        *(uint4*)(Wsm + j * WS + c8) = *(const uint4*)(gW + j * 64 + c8);
    }
#pragma unroll
    for (int it = 0; it < 4; it++) {
        int idx = it * 256 + tid;
        int n = idx >> 5, c2 = (idx & 31) * 2;
        float2 v = *(const float2*)(g_h + (size_t)(base + n) * 64 + c2);
        *(__half2*)(Hsm + n * WS + c2) = __floats2half2_rn(v.x, v.y);
    }
    __syncthreads();

    int warp = tid >> 5, lane = tid & 31;
    int mw = warp & 1;
    int nw = warp >> 1;
    int g = lane >> 2, t = lane & 3;

    float acc[8][4];
#pragma unroll
    for (int nb = 0; nb < 8; nb++)
#pragma unroll
        for (int q = 0; q < 4; q++) acc[nb][q] = 0.f;

    const __half* hA0 = Hsm + (mw * 16 + g) * WS + t * 2;
    const __half* hA1 = hA0 + 8 * WS;
    const __half* wB = Wsm + (size_t)(nw * 64 + g) * WS + t * 2;

#pragma unroll
    for (int k = 0; k < 4; k++) {
        int c0 = k * 16;
        unsigned a0 = *(const unsigned*)(hA0 + c0);
        unsigned a1 = *(const unsigned*)(hA1 + c0);
        unsigned a2 = *(const unsigned*)(hA0 + c0 + 8);
        unsigned a3 = *(const unsigned*)(hA1 + c0 + 8);
#pragma unroll
        for (int nb = 0; nb < 8; nb++) {
            unsigned b0 = *(const unsigned*)(wB + nb * 8 * WS + c0);
            unsigned b1 = *(const unsigned*)(wB + nb * 8 * WS + c0 + 8);
            asm volatile(
                "mma.sync.aligned.m16n8k16.row.col.f32.f16.f16.f32 "
                "{%0,%1,%2,%3}, {%4,%5,%6,%7}, {%8,%9}, {%0,%1,%2,%3};"
                : "+f"(acc[nb][0]), "+f"(acc[nb][1]), "+f"(acc[nb][2]), "+f"(acc[nb][3])
                : "r"(a0), "r"(a1), "r"(a2), "r"(a3), "r"(b0), "r"(b1));
        }
    }

    int n0 = base + mw * 16 + g;
#pragma unroll
    for (int nb = 0; nb < 8; nb++) {
        int j = nw * 64 + nb * 8 + t * 2;
        *(__half2*)(g_xh + (size_t)n0 * 256 + j) = __floats2half2_rn(acc[nb][0], acc[nb][1]);
        *(__half2*)(g_xh + (size_t)(n0 + 8) * 256 + j) = __floats2half2_rn(acc[nb][2], acc[nb][3]);
    }
}

// ---------------- node kernel: f32x2 packed FMA (measured ~99us) ----------------
__global__ void __launch_bounds__(256, 6)
k_node(const float* __restrict__ cb, const float* __restrict__ lg,
       const float* __restrict__ lb) {
    __shared__ float se[8][32][4];
    int warp = threadIdx.x >> 5, lane = threadIdx.x & 31;
    int n = blockIdx.x * 8 + warp;
    int row = g_rowstart[n];
    int deg = g_deg[n];
    int my_h = lane >> 3;
    int cbase = (lane & 7) * 8;
    float4 ad4 = *(const float4*)(g_ad + (size_t)n * 4);

    ull a01 = 0ull, a23 = 0ull, a45 = 0ull, a67 = 0ull;
    float4 sum4 = make_float4(0.f, 0.f, 0.f, 0.f);

    for (int base = 0; base < deg; base += 32) {
        int i = base + lane;
        int s_l = 0;
        if (i < deg) {
            s_l = __ldg(g_csrc + row + i);
            float4 a4 = *(const float4*)(g_as + (size_t)s_l * 4);
            float4 e4;
            e4.x = __expf(lrelu(a4.x + ad4.x));
            e4.y = __expf(lrelu(a4.y + ad4.y));
            e4.z = __expf(lrelu(a4.z + ad4.z));
            e4.w = __expf(lrelu(a4.w + ad4.w));
            sum4.x += e4.x; sum4.y += e4.y; sum4.z += e4.z; sum4.w += e4.w;
            *(float4*)&se[warp][lane][0] = e4;
        }
        __syncwarp();
        int cnt = min(32, deg - base);
#pragma unroll 4
        for (int k = 0; k < cnt; k++) {
            int s = __shfl_sync(0xffffffffu, s_l, k);
            float a = se[warp][k][my_h];
            ull aa = pk2(a, a);
            uint4 raw = __ldg((const uint4*)(g_xh + (size_t)s * 256 + lane * 8));
            float2 f0 = __half22float2(*reinterpret_cast<__half2*>(&raw.x));
            float2 f1 = __half22float2(*reinterpret_cast<__half2*>(&raw.y));
            float2 f2 = __half22float2(*reinterpret_cast<__half2*>(&raw.z));
            float2 f3 = __half22float2(*reinterpret_cast<__half2*>(&raw.w));
            a01 = fma2(pk2(f0.x, f0.y), aa, a01);
            a23 = fma2(pk2(f1.x, f1.y), aa, a23);
            a45 = fma2(pk2(f2.x, f2.y), aa, a45);
            a67 = fma2(pk2(f3.x, f3.y), aa, a67);
        }
        __syncwarp();
    }

    float acc[8];
    { float2 r = upk2(a01); acc[0] = r.x; acc[1] = r.y; }
    { float2 r = upk2(a23); acc[2] = r.x; acc[3] = r.y; }
    { float2 r = upk2(a45); acc[4] = r.x; acc[5] = r.y; }
    { float2 r = upk2(a67); acc[6] = r.x; acc[7] = r.y; }

#pragma unroll
    for (int o = 16; o; o >>= 1) {
        sum4.x += __shfl_xor_sync(0xffffffffu, sum4.x, o);
        sum4.y += __shfl_xor_sync(0xffffffffu, sum4.y, o);
        sum4.z += __shfl_xor_sync(0xffffffffu, sum4.z, o);
        sum4.w += __shfl_xor_sync(0xffffffffu, sum4.w, o);
    }
    float sh = (my_h == 0) ? sum4.x : (my_h == 1) ? sum4.y : (my_h == 2) ? sum4.z : sum4.w;
    float rr = 0.25f / (sh + 1e-16f);
#pragma unroll
    for (int k = 0; k < 8; k++) acc[k] *= rr;

#pragma unroll
    for (int k = 0; k < 8; k++) {
        acc[k] += __shfl_xor_sync(0xffffffffu, acc[k], 8);
        acc[k] += __shfl_xor_sync(0xffffffffu, acc[k], 16);
    }

    float v[8], psum = 0.f, psq = 0.f;
#pragma unroll
    for (int k = 0; k < 8; k++) {
        v[k] = acc[k] + cb[cbase + k];
        psum += v[k];
        psq += v[k] * v[k];
    }
#pragma unroll
    for (int o = 4; o; o >>= 1) {
        psum += __shfl_xor_sync(0xffffffffu, psum, o);
        psq  += __shfl_xor_sync(0xffffffffu, psq, o);
    }
    float mu = psum * (1.f / 64.f);
    float var = psq * (1.f / 64.f) - mu * mu;
    float rs = rsqrtf(var + 1e-5f);

    if (lane < 8) {
        float* hp = g_h + (size_t)n * 64 + cbase;
        float4 o0 = *(float4*)hp;
        float4 o1 = *(float4*)(hp + 4);
        float y;
        y = (v[0] - mu) * rs * lg[cbase + 0] + lb[cbase + 0]; o0.x += fmaxf(y, 0.f);
        y = (v[1] - mu) * rs * lg[cbase + 1] + lb[cbase + 1]; o0.y += fmaxf(y, 0.f);
        y = (v[2] - mu) * rs * lg[cbase + 2] + lb[cbase + 2]; o0.z += fmaxf(y, 0.f);
        y = (v[3] - mu) * rs * lg[cbase + 3] + lb[cbase + 3]; o0.w += fmaxf(y, 0.f);
        y = (v[4] - mu) * rs * lg[cbase + 4] + lb[cbase + 4]; o1.x += fmaxf(y, 0.f);
        y = (v[5] - mu) * rs * lg[cbase + 5] + lb[cbase + 5]; o1.y += fmaxf(y, 0.f);
        y = (v[6] - mu) * rs * lg[cbase + 6] + lb[cbase + 6]; o1.z += fmaxf(y, 0.f);
        y = (v[7] - mu) * rs * lg[cbase + 7] + lb[cbase + 7]; o1.w += fmaxf(y, 0.f);
        *(float4*)hp = o0;
        *(float4*)(hp + 4) = o1;
    }
}

// out: 4 nodes per thread (weight LDS amortized 4x)
__global__ void k_out(const float* __restrict__ oW, const float* __restrict__ ob,
                      float* __restrict__ out) {
    __shared__ float sW[32 * 65];
    __shared__ float sob[32];
    for (int i = threadIdx.x; i < 32 * 64; i += 256) {
        int o = i >> 6, k = i & 63;
        sW[o * 65 + k] = oW[i];
    }
    if (threadIdx.x < 32) sob[threadIdx.x] = ob[threadIdx.x];
    __syncthreads();

    int idx = blockIdx.x * 256 + threadIdx.x;   // grid = NN*OO/(256*4) = 3125
    int n0 = (idx >> 5) * 4;                    // 4 consecutive nodes
    int o = idx & 31;
    float acc[4] = {sob[o], sob[o], sob[o], sob[o]};
    const float* wr = sW + o * 65;
    const float4* h0 = (const float4*)(g_h + (size_t)n0 * 64);
#pragma unroll
    for (int i = 0; i < 16; i++) {
        float w0 = wr[i * 4], w1 = wr[i * 4 + 1], w2 = wr[i * 4 + 2], w3 = wr[i * 4 + 3];
#pragma unroll
        for (int j = 0; j < 4; j++) {
            float4 hv = h0[j * 16 + i];
            acc[j] += hv.x * w0 + hv.y * w1 + hv.z * w2 + hv.w * w3;
        }
    }
#pragma unroll
    for (int j = 0; j < 4; j++)
        out[(size_t)(n0 + j) * OO + o] = acc[j];
}

// ---------------- launch ----------------
extern "C" void kernel_launch(void* const* d_in, const int* in_sizes, int n_in,
                              void* d_out, int out_size) {
    const float* x = (const float*)d_in[0];
    const int* eidx;
    const float* dfeat;
    if (in_sizes[1] == GG * DF) { dfeat = (const float*)d_in[1]; eidx = (const int*)d_in[2]; }
    else                        { eidx = (const int*)d_in[1];    dfeat = (const float*)d_in[2]; }
    const int*   batch = (const int*)d_in[3];
    const float* nW = (const float*)d_in[4];
    const float* nb = (const float*)d_in[5];
    const float* dW = (const float*)d_in[6];
    const float* db = (const float*)d_in[7];
    const float* W0  = (const float*)d_in[8];
    const float* as0 = (const float*)d_in[9];
    const float* ad0 = (const float*)d_in[10];
    const float* cb0 = (const float*)d_in[11];
    const float* lg0 = (const float*)d_in[12];
    const float* lb0 = (const float*)d_in[13];
    const float* W1  = (const float*)d_in[14];
    const float* as1 = (const float*)d_in[15];
    const float* ad1 = (const float*)d_in[16];
    const float* cb1 = (const float*)d_in[17];
    const float* lg1 = (const float*)d_in[18];
    const float* lb1 = (const float*)d_in[19];
    const float* oW = (const float*)d_in[20];
    const float* ob = (const float*)d_in[21];
    const int* srcA = eidx;
    const int* dstA = eidx + EE;

    cudaFuncSetAttribute(k_tmma, cudaFuncAttributeMaxDynamicSharedMemorySize, SMEM_MMA);

    k_pre<<<PRE_B, 256>>>(dfeat, dW, db, W0, W1, nW);                 // 1
    k_hinit_t<<<NN / 32, 256>>>(x, batch, nb);                        // 2
    k_va2<<<16, 512>>>(W0, as0, ad0, W1, as1, ad1);                   // 3
    k_alpha<<<(NN * 32 + 255) / 256, 256>>>(0);                       // 4 <- profiled
    k_tmma<<<NN / MT, 256, SMEM_MMA>>>(0);                            // 5
    k_hist<<<(ETOT + 255) / 256, 256>>>(dstA);
    k_scan1<<<NB, SB>>>();
    k_scan2<<<1, 256>>>();
    k_scan3<<<(NN + 255) / 256, 256>>>();
    k_scat<<<(ETOT + 255) / 256, 256>>>(srcA, dstA);
    k_node<<<NN / 8, 256>>>(cb0, lg0, lb0);

    k_alpha<<<(NN * 32 + 255) / 256, 256>>>(1);
    k_tmma<<<NN / MT, 256, SMEM_MMA>>>(1);
    k_node<<<NN / 8, 256>>>(cb1, lg1, lb1);

    k_out<<<NN * OO / 1024, 256>>>(oW, ob, (float*)d_out);
}